// round 4
// baseline (speedup 1.0000x reference)
#include <cuda_runtime.h>
#include <math.h>

#define LL     1632
#define NUP    8
#define NB     32
#define NA     64
#define RED    408
#define RWS    8

typedef unsigned long long ull;

// ---------------- scratch (device globals) -----------------------------------
__device__ float2 g_phtab[LL];          // e^{2*pi*i*q/L}
__device__ float2 g_b12[12];            // e^{2*pi*i*r/12}
__device__ int    g_m[NUP*NB];          // per (u,b) peak position m
__device__ ull    g_Weff2[NUP*NB*180];  // per (u,b): 3 classes x 12 x 5, packed {w,w}
__device__ float  g_win[1024*21];       // per-block partial windows
__device__ float  g_noise[1024];        // per-block partial noise sums

// ---------------- f32x2 helpers ----------------------------------------------
__device__ __forceinline__ ull pk2(float a, float b) {
    ull r; asm("mov.b64 %0, {%1, %2};" : "=l"(r) : "f"(a), "f"(b)); return r;
}
__device__ __forceinline__ float2 up2(ull v) {
    float2 r; asm("mov.b64 {%0, %1}, %2;" : "=f"(r.x), "=f"(r.y) : "l"(v)); return r;
}
__device__ __forceinline__ ull fma2_(ull a, ull b, ull c) {
    ull d; asm("fma.rn.f32x2 %0, %1, %2, %3;" : "=l"(d) : "l"(a), "l"(b), "l"(c)); return d;
}
__device__ __forceinline__ ull mul2_(ull a, ull b) {
    ull d; asm("mul.rn.f32x2 %0, %1, %2;" : "=l"(d) : "l"(a), "l"(b)); return d;
}
// complex multiply: a={ax,ay} times b given as bxx={bx,bx}, byn={-by,by}
__device__ __forceinline__ ull cm2(ull a, ull bxx, ull byn) {
    float2 v = up2(a);
    return fma2_(pk2(v.y, v.x), byn, mul2_(a, bxx));
}
// complex square of packed a
__device__ __forceinline__ ull sq2(ull a) {
    float2 v = up2(a);
    return fma2_(pk2(v.y, v.x), pk2(-v.y, v.y), mul2_(a, pk2(v.x, v.x)));
}

// ---------------- kernel P: tables -------------------------------------------
__global__ void kP() {
    int i = blockIdx.x * blockDim.x + threadIdx.x;
    const double TP = 6.283185307179586476925286766559;
    if (i < LL) {
        double ang = TP * (double)i / (double)LL;
        g_phtab[i] = make_float2((float)cos(ang), (float)sin(ang));
    }
    if (i < 12) {
        double ang = TP * (double)i / 12.0;
        g_b12[i] = make_float2((float)cos(ang), (float)sin(ang));
    }
}

// ---------------- kernel A: 21-bin DFT window power + noise ------------------
__device__ __forceinline__ float wred(float v) {
    #pragma unroll
    for (int off = 16; off; off >>= 1) v += __shfl_xor_sync(0xffffffffu, v, off);
    return v;
}

__global__ __launch_bounds__(256, 2) void kA(const float* __restrict__ lsr,
                                             const float* __restrict__ lsi,
                                             const int*   __restrict__ cs) {
    __shared__ float2 ph[LL];
    __shared__ float  win[22];

    const int tid  = threadIdx.x;
    const int bid  = blockIdx.x;
    const int part = bid & 3;
    const int ub   = bid >> 2;
    const int u    = ub >> 5;

    for (int i = tid; i < LL; i += 256) ph[i] = g_phtab[i];
    if (tid < 22) win[tid] = 0.f;
    __syncthreads();

    int k12 = (12 - (cs[u] % 12)) % 12; if (k12 < 0) k12 += 12;

    const int lane = tid & 31;
    const int warp = tid >> 5;
    const int a0   = part * 16 + warp * 2;
    const int base0 = (ub * 64 + a0) * LL;
    const int base1 = base0 + LL;

    // packed accumulators: AB[o] = {sum g_r*cos, sum g_r*sin}, CD[o] = {sum g_i*cos, sum g_i*sin}
    ull AB0[10], CD0[10], AB1[10], CD1[10];
    #pragma unroll
    for (int o = 0; o < 10; ++o) { AB0[o]=0ull; CD0[o]=0ull; AB1[o]=0ull; CD1[o]=0ull; }
    float s0r=0.f, s0i=0.f, s1r=0.f, s1i=0.f, nacc=0.f;

    // base twiddle sequence: index (n*k12)%12 steps by (32*k12)%12 -> period 3
    const int st = (8 * k12) % 12;
    int r = (lane * k12) % 12;
    float2 bb0 = g_b12[r]; r += st; if (r >= 12) r -= 12;
    float2 bb1 = g_b12[r]; r += st; if (r >= 12) r -= 12;
    float2 bb2 = g_b12[r];

    #pragma unroll 3
    for (int k = 0; k < 51; ++k) {
        const int n = lane + (k << 5);
        float x0r = lsr[base0 + n], x0i = lsi[base0 + n];
        float x1r = lsr[base1 + n], x1i = lsi[base1 + n];
        if (n < LL - 1) {
            float d0r = lsr[base0 + n + 1] - x0r, d0i = lsi[base0 + n + 1] - x0i;
            float d1r = lsr[base1 + n + 1] - x1r, d1i = lsi[base1 + n + 1] - x1i;
            nacc += d0r*d0r + d0i*d0i + d1r*d1r + d1i*d1i;
        }
        const int km = k % 3;            // resolved at compile time (unroll 3)
        float2 b = (km == 0) ? bb0 : ((km == 1) ? bb1 : bb2);

        float g0r = x0r*b.x - x0i*b.y, g0i = fmaf(x0r, b.y, x0i*b.x);
        float g1r = x1r*b.x - x1i*b.y, g1i = fmaf(x1r, b.y, x1i*b.x);
        s0r += g0r; s0i += g0i; s1r += g1r; s1i += g1i;

        const ull g0rb = pk2(g0r, g0r), g0ib = pk2(g0i, g0i);
        const ull g1rb = pk2(g1r, g1r), g1ib = pk2(g1i, g1i);

        // chirp squaring tree: t_o = e^{2*pi*i*n*o/L}, packed {cos,sin}
        const float2 w = ph[n];
        const ull t1   = pk2(w.x, w.y);
        const ull b1xx = pk2(w.x, w.x);
        const ull b1yn = pk2(-w.y, w.y);

        #define ACC(o, t) do { \
            AB0[o] = fma2_(g0rb, (t), AB0[o]); CD0[o] = fma2_(g0ib, (t), CD0[o]); \
            AB1[o] = fma2_(g1rb, (t), AB1[o]); CD1[o] = fma2_(g1ib, (t), CD1[o]); } while (0)

        ACC(0, t1);
        ull t2 = sq2(t1);          ACC(1, t2);
        ull t3 = cm2(t2, b1xx, b1yn); ACC(2, t3);
        ull t4 = sq2(t2);          ACC(3, t4);
        ull t5 = cm2(t4, b1xx, b1yn); ACC(4, t5);
        ull t6 = sq2(t3);          ACC(5, t6);
        ull t7 = cm2(t6, b1xx, b1yn); ACC(6, t7);
        ull t8 = sq2(t4);          ACC(7, t8);
        ull t9 = cm2(t8, b1xx, b1yn); ACC(8, t9);
        ull ta = sq2(t5);          ACC(9, ta);
        #undef ACC
    }

    float A0[10], B0[10], C0[10], D0[10];
    float A1[10], B1[10], C1[10], D1[10];
    #pragma unroll
    for (int o = 0; o < 10; ++o) {
        float2 v;
        v = up2(AB0[o]); A0[o] = wred(v.x); B0[o] = wred(v.y);
        v = up2(CD0[o]); C0[o] = wred(v.x); D0[o] = wred(v.y);
        v = up2(AB1[o]); A1[o] = wred(v.x); B1[o] = wred(v.y);
        v = up2(CD1[o]); C1[o] = wred(v.x); D1[o] = wred(v.y);
    }
    s0r=wred(s0r); s0i=wred(s0i); s1r=wred(s1r); s1i=wred(s1i); nacc=wred(nacc);

    if (lane == 0) {
        atomicAdd(&win[10], s0r*s0r + s0i*s0i + s1r*s1r + s1i*s1i);
        #pragma unroll
        for (int o = 0; o < 10; ++o) {
            float rp0 = A0[o]-D0[o], ip0 = B0[o]+C0[o];
            float rp1 = A1[o]-D1[o], ip1 = B1[o]+C1[o];
            atomicAdd(&win[11+o], rp0*rp0 + ip0*ip0 + rp1*rp1 + ip1*ip1);
            float rm0 = A0[o]+D0[o], im0 = C0[o]-B0[o];
            float rm1 = A1[o]+D1[o], im1 = C1[o]-B1[o];
            atomicAdd(&win[9-o],  rm0*rm0 + im0*im0 + rm1*rm1 + im1*im1);
        }
        atomicAdd(&win[21], nacc);
    }
    __syncthreads();
    if (tid < 21) g_win[bid * 21 + tid] = win[tid];
    if (tid == 21) g_noise[bid] = win[21];
}

// ---------------- kernel S: argmax + Wiener solve + packed Weff --------------
__global__ void kS(const int* __restrict__ cs) {
    __shared__ float win[21];
    __shared__ float Cm[144], Am[144], Iv[144], Wsh[144];
    __shared__ float s_sh;

    const int ub = blockIdx.x;
    const int tid = threadIdx.x;           // 144 threads
    const int u = ub >> 5;
    const int i = tid / 12, j = tid % 12;

    if (tid < 21) {
        float s = 0.f;
        #pragma unroll
        for (int p = 0; p < 4; ++p) s += g_win[(ub * 4 + p) * 21 + tid];
        win[tid] = s;
    }
    if (tid == 21) {
        float s = 0.f;
        #pragma unroll
        for (int p = 0; p < 4; ++p) s += g_noise[ub * 4 + p];
        s_sh = s / (64.0f * 1631.0f * 2.0f);
    }
    __syncthreads();

    if (tid == 0) {
        int bi = 0; float bv = win[0];
        for (int q = 1; q < 21; ++q) if (win[q] > bv) { bv = win[q]; bi = q; }
        int k12 = (12 - (cs[u] % 12)) % 12; if (k12 < 0) k12 += 12;
        g_m[ub] = k12 * 136 + (bi - 10);
    }

    int d = i - j; if (d < 0) d = -d;
    float c = (float)pow(0.9, (double)d);
    Cm[tid] = c;
    Am[tid] = c + ((i == j) ? s_sh : 0.f);
    Iv[tid] = (i == j) ? 1.f : 0.f;
    __syncthreads();

    for (int k = 0; k < 12; ++k) {
        float piv = Am[k * 12 + k];
        __syncthreads();
        if (i == k) {
            float ip = 1.0f / piv;
            Am[tid] *= ip; Iv[tid] *= ip;
        }
        __syncthreads();
        float f   = Am[i * 12 + k];
        float akj = Am[k * 12 + j];
        float ikj = Iv[k * 12 + j];
        __syncthreads();
        if (i != k) {
            Am[tid] = fmaf(-f, akj, Am[tid]);
            Iv[tid] = fmaf(-f, ikj, Iv[tid]);
        }
        __syncthreads();
    }

    float w = 0.f;
    #pragma unroll
    for (int k2 = 0; k2 < 12; ++k2) w = fmaf(Cm[i * 12 + k2], Iv[k2 * 12 + j], w);
    Wsh[tid] = w;
    __syncthreads();

    // Weff[class][i][s] = sum_j W[i][j] * Lerp[class][j][s], packed {w,w}
    for (int item = tid; item < 180; item += 144) {
        const int cl  = item / 60;
        const int rem = item - cl * 60;
        const int ii  = rem / 5;
        const int s   = rem - ii * 5;
        const int rep = (cl == 0) ? 0 : ((cl == 1) ? 1 : 135);
        const int hb  = 3 * rep - 1;
        float acc = 0.f;
        #pragma unroll
        for (int jj = 0; jj < 12; ++jj) {
            float t = (float)(rep * 12 + jj);
            float p = (t - 1.5f) * 0.25f;
            p = fminf(fmaxf(p, 0.f), 407.f);
            int i0 = (int)p; if (i0 > 406) i0 = 406;
            float fr = p - (float)i0;
            int s0 = i0 - hb;
            float coef = (s == s0) ? (1.f - fr) : ((s == s0 + 1) ? fr : 0.f);
            acc = fmaf(Wsh[ii * 12 + jj], coef, acc);
        }
        g_Weff2[ub * 180 + item] = pk2(acc, acc);
    }
}

// ---------------- kernel B: phase + 4-avg + folded 5-tap stencil -------------
__global__ __launch_bounds__(256) void kB(const float* __restrict__ lsr,
                                          const float* __restrict__ lsi,
                                          float2* __restrict__ out) {
    __shared__ float2 ph[LL];
    __shared__ ull    hv[RWS * RED];    // packed {hr,hi}
    __shared__ ull    We2[180];

    const int tid  = threadIdx.x;
    const int row0 = blockIdx.x * RWS;      // RWS rows, same ub
    const int ub   = row0 >> 6;

    if (tid < 180) We2[tid] = g_Weff2[ub * 180 + tid];
    const int m  = g_m[ub];
    const int mm = ((m % LL) + LL) % LL;

    // incremental phase table fill: q = (n*mm) % LL
    {
        int q = (tid * mm) % LL;
        const int stp = (256 * mm) % LL;
        for (int n = tid; n < LL; n += 256) {
            ph[n] = g_phtab[q];
            q += stp; if (q >= LL) q -= LL;
        }
    }
    __syncthreads();

    // stage 1: phase-shifted 4-tap average
    #pragma unroll
    for (int rl = 0; rl < RWS; ++rl) {
        const int rbase = (row0 + rl) * LL;
        for (int rr = tid; rr < RED; rr += 256) {
            const float4 xr = *(const float4*)(lsr + rbase + 4 * rr);
            const float4 xi = *(const float4*)(lsi + rbase + 4 * rr);
            const float2 p0 = ph[4*rr], p1 = ph[4*rr+1], p2 = ph[4*rr+2], p3 = ph[4*rr+3];
            float sr, si;
            sr = xr.x * p0.x;              si = xr.x * p0.y;
            sr = fmaf(-xi.x, p0.y, sr);    si = fmaf( xi.x, p0.x, si);
            sr = fmaf( xr.y, p1.x, sr);    si = fmaf( xr.y, p1.y, si);
            sr = fmaf(-xi.y, p1.y, sr);    si = fmaf( xi.y, p1.x, si);
            sr = fmaf( xr.z, p2.x, sr);    si = fmaf( xr.z, p2.y, si);
            sr = fmaf(-xi.z, p2.y, sr);    si = fmaf( xi.z, p2.x, si);
            sr = fmaf( xr.w, p3.x, sr);    si = fmaf( xr.w, p3.y, si);
            sr = fmaf(-xi.w, p3.y, sr);    si = fmaf( xi.w, p3.x, si);
            hv[rl * RED + rr] = pk2(sr * 0.25f, si * 0.25f);
        }
    }
    __syncthreads();

    // stage 2: per (row, blk) item -> 12 outputs via packed 5-tap stencil
    for (int item = tid; item < RWS * 136; item += 256) {
        const int rl  = item / 136;
        const int blk = item - rl * 136;
        const int cl  = (blk == 0) ? 0 : ((blk == 135) ? 2 : 1);
        const ull* w  = &We2[cl * 60];
        const int hb  = 3 * blk - 1;
        const int hbase = rl * RED;

        ull h[5];
        #pragma unroll
        for (int s = 0; s < 5; ++s) {
            int idx = hb + s;
            idx = (idx < 0) ? 0 : ((idx > RED - 1) ? RED - 1 : idx);
            h[s] = hv[hbase + idx];
        }

        float2 res[12];
        #pragma unroll
        for (int i = 0; i < 12; ++i) {
            ull acc = mul2_(w[i * 5], h[0]);
            acc = fma2_(w[i * 5 + 1], h[1], acc);
            acc = fma2_(w[i * 5 + 2], h[2], acc);
            acc = fma2_(w[i * 5 + 3], h[3], acc);
            acc = fma2_(w[i * 5 + 4], h[4], acc);
            res[i] = up2(acc);
        }

        float4* op = (float4*)(out + (row0 + rl) * LL + blk * 12);
        #pragma unroll
        for (int q = 0; q < 6; ++q)
            op[q] = make_float4(res[2*q].x, res[2*q].y, res[2*q+1].x, res[2*q+1].y);
    }
}

// ---------------- launcher ----------------------------------------------------
extern "C" void kernel_launch(void* const* d_in, const int* in_sizes, int n_in,
                              void* d_out, int out_size) {
    const float* lsr = (const float*)d_in[0];
    const float* lsi = (const float*)d_in[1];
    const int*   cs  = (const int*)d_in[2];
    float2* out = (float2*)d_out;

    kP<<<7, 256>>>();
    kA<<<1024, 256>>>(lsr, lsi, cs);
    kS<<<NUP * NB, 144>>>(cs);
    kB<<<NUP * NB * NA / RWS, 256>>>(lsr, lsi, out);
    (void)in_sizes; (void)n_in; (void)out_size;
}

// round 5
// speedup vs baseline: 1.1334x; 1.1334x over previous
#include <cuda_runtime.h>
#include <math.h>

#define LL     1632
#define NUP    8
#define NB     32
#define NA     64
#define RED    408
#define RWS    4

typedef unsigned long long ull;

// ---------------- scratch (device globals) -----------------------------------
__device__ float2 g_phtab[LL];          // e^{2*pi*i*q/L}
__device__ float2 g_b12[12];            // e^{2*pi*i*r/12}
__device__ int    g_m[NUP*NB];          // per (u,b) peak position m
__device__ ull    g_Weff2[NUP*NB*180];  // per (u,b): 3 classes x 12 x 5, packed {w,w}
__device__ float  g_win[1024*21];       // per-block partial windows
__device__ float  g_noise[1024];        // per-block partial noise sums

// ---------------- f32x2 helpers (kB only) ------------------------------------
__device__ __forceinline__ ull pk2(float a, float b) {
    ull r; asm("mov.b64 %0, {%1, %2};" : "=l"(r) : "f"(a), "f"(b)); return r;
}
__device__ __forceinline__ float2 up2(ull v) {
    float2 r; asm("mov.b64 {%0, %1}, %2;" : "=f"(r.x), "=f"(r.y) : "l"(v)); return r;
}
__device__ __forceinline__ ull fma2_(ull a, ull b, ull c) {
    ull d; asm("fma.rn.f32x2 %0, %1, %2, %3;" : "=l"(d) : "l"(a), "l"(b), "l"(c)); return d;
}
__device__ __forceinline__ ull mul2_(ull a, ull b) {
    ull d; asm("mul.rn.f32x2 %0, %1, %2;" : "=l"(d) : "l"(a), "l"(b)); return d;
}

// ---------------- kernel P: tables -------------------------------------------
__global__ void kP() {
    int i = blockIdx.x * blockDim.x + threadIdx.x;
    const double TP = 6.283185307179586476925286766559;
    if (i < LL) {
        double ang = TP * (double)i / (double)LL;
        g_phtab[i] = make_float2((float)cos(ang), (float)sin(ang));
    }
    if (i < 12) {
        double ang = TP * (double)i / 12.0;
        g_b12[i] = make_float2((float)cos(ang), (float)sin(ang));
    }
}

// ---------------- kernel A: 21-bin DFT window power + noise ------------------
// mirror symmetry: pair n with 1632-n; cos even, sin odd; b(1632-n) = conj(b(n))
__device__ __forceinline__ float wred(float v) {
    #pragma unroll
    for (int off = 16; off; off >>= 1) v += __shfl_xor_sync(0xffffffffu, v, off);
    return v;
}

__global__ __launch_bounds__(256, 2) void kA(const float* __restrict__ lsr,
                                             const float* __restrict__ lsi,
                                             const int*   __restrict__ cs) {
    __shared__ float2 ph[817];
    __shared__ float2 b12s[12];
    __shared__ float  win[22];

    const int tid  = threadIdx.x;
    const int bid  = blockIdx.x;
    const int part = bid & 3;
    const int ub   = bid >> 2;
    const int u    = ub >> 5;

    for (int i = tid; i < 817; i += 256) ph[i] = g_phtab[i];
    if (tid < 12) b12s[tid] = g_b12[tid];
    if (tid < 22) win[tid] = 0.f;
    __syncthreads();

    int k12 = (12 - (cs[u] % 12)) % 12; if (k12 < 0) k12 += 12;

    const int lane = tid & 31;
    const int warp = tid >> 5;
    const int a0   = part * 16 + warp * 2;
    const int base0 = (ub * 64 + a0) * LL;
    const int base1 = base0 + LL;

    float A0[10], B0[10], C0[10], D0[10];
    float A1[10], B1[10], C1[10], D1[10];
    #pragma unroll
    for (int o = 0; o < 10; ++o) {
        A0[o]=B0[o]=C0[o]=D0[o]=0.f;
        A1[o]=B1[o]=C1[o]=D1[o]=0.f;
    }
    float s0r=0.f, s0i=0.f, s1r=0.f, s1i=0.f, nacc=0.f;

    const int st = (8 * k12) % 12;       // (32*k12) mod 12
    int r = (lane * k12) % 12;

    for (int k = 0; k < 26; ++k) {
        const int n  = lane + (k << 5);
        const int nm = LL - n;
        const bool act = (n <= 816);
        const bool mir = (n >= 1 && n <= 815);
        const bool mnz = (n >= 2 && n <= 815);

        float2 b = b12s[r];
        r += st; if (r >= 12) r -= 12;

        float x0r=0.f,x0i=0.f,x1r=0.f,x1i=0.f;
        float m0r=0.f,m0i=0.f,m1r=0.f,m1i=0.f;
        if (act) {
            x0r = lsr[base0+n]; x0i = lsi[base0+n];
            x1r = lsr[base1+n]; x1i = lsi[base1+n];
            float y0r = lsr[base0+n+1], y0i = lsi[base0+n+1];
            float y1r = lsr[base1+n+1], y1i = lsi[base1+n+1];
            float d0r = y0r-x0r, d0i = y0i-x0i, d1r = y1r-x1r, d1i = y1i-x1i;
            nacc += d0r*d0r + d0i*d0i + d1r*d1r + d1i*d1i;
        }
        if (mir) {
            m0r = lsr[base0+nm]; m0i = lsi[base0+nm];
            m1r = lsr[base1+nm]; m1i = lsi[base1+nm];
        }
        if (mnz) {
            float z0r = lsr[base0+nm+1], z0i = lsi[base0+nm+1];
            float z1r = lsr[base1+nm+1], z1i = lsi[base1+nm+1];
            float e0r = z0r-m0r, e0i = z0i-m0i, e1r = z1r-m1r, e1i = z1i-m1i;
            nacc += e0r*e0r + e0i*e0i + e1r*e1r + e1i*e1i;
        }
        if (!act) continue;

        // g(n) = x * b ; g(nm) = m * conj(b)
        float g0r = x0r*b.x - x0i*b.y, g0i = fmaf(x0r, b.y, x0i*b.x);
        float g1r = x1r*b.x - x1i*b.y, g1i = fmaf(x1r, b.y, x1i*b.x);
        float h0r = fmaf(m0i, b.y,  m0r*b.x), h0i = fmaf(m0i, b.x, -(m0r*b.y));
        float h1r = fmaf(m1i, b.y,  m1r*b.x), h1i = fmaf(m1i, b.x, -(m1r*b.y));

        float sr0 = g0r+h0r, dr0 = g0r-h0r, si0 = g0i+h0i, di0 = g0i-h0i;
        float sr1 = g1r+h1r, dr1 = g1r-h1r, si1 = g1i+h1i, di1 = g1i-h1i;
        s0r += sr0; s0i += si0; s1r += sr1; s1i += si1;

        // Chebyshev chirp: c_o = cos(2*pi*n*o/L), s_o = sin(...)
        const float2 w = ph[n];
        float cp = 1.f, sp = 0.f;
        float cc = w.x, sc = w.y;
        const float twoc = w.x + w.x;
        #pragma unroll
        for (int o = 0; o < 10; ++o) {
            A0[o] = fmaf(sr0, cc, A0[o]); B0[o] = fmaf(dr0, sc, B0[o]);
            C0[o] = fmaf(si0, cc, C0[o]); D0[o] = fmaf(di0, sc, D0[o]);
            A1[o] = fmaf(sr1, cc, A1[o]); B1[o] = fmaf(dr1, sc, B1[o]);
            C1[o] = fmaf(si1, cc, C1[o]); D1[o] = fmaf(di1, sc, D1[o]);
            if (o < 9) {
                float cn = fmaf(twoc, cc, -cp);
                float sn = fmaf(twoc, sc, -sp);
                cp = cc; cc = cn; sp = sc; sc = sn;
            }
        }
    }

    #pragma unroll
    for (int o = 0; o < 10; ++o) {
        A0[o]=wred(A0[o]); B0[o]=wred(B0[o]); C0[o]=wred(C0[o]); D0[o]=wred(D0[o]);
        A1[o]=wred(A1[o]); B1[o]=wred(B1[o]); C1[o]=wred(C1[o]); D1[o]=wred(D1[o]);
    }
    s0r=wred(s0r); s0i=wred(s0i); s1r=wred(s1r); s1i=wred(s1i); nacc=wred(nacc);

    if (lane == 0) {
        atomicAdd(&win[10], s0r*s0r + s0i*s0i + s1r*s1r + s1i*s1i);
        #pragma unroll
        for (int o = 0; o < 10; ++o) {
            float rp0 = A0[o]-D0[o], ip0 = B0[o]+C0[o];
            float rp1 = A1[o]-D1[o], ip1 = B1[o]+C1[o];
            atomicAdd(&win[11+o], rp0*rp0 + ip0*ip0 + rp1*rp1 + ip1*ip1);
            float rm0 = A0[o]+D0[o], im0 = C0[o]-B0[o];
            float rm1 = A1[o]+D1[o], im1 = C1[o]-B1[o];
            atomicAdd(&win[9-o],  rm0*rm0 + im0*im0 + rm1*rm1 + im1*im1);
        }
        atomicAdd(&win[21], nacc);
    }
    __syncthreads();
    if (tid < 21) g_win[bid * 21 + tid] = win[tid];
    if (tid == 21) g_noise[bid] = win[21];
}

// ---------------- kernel S: argmax + Wiener solve + packed Weff --------------
__global__ void kS(const int* __restrict__ cs) {
    __shared__ float win[21];
    __shared__ float Cm[144], Am[144], Iv[144], Wsh[144];
    __shared__ float s_sh;

    const int ub = blockIdx.x;
    const int tid = threadIdx.x;           // 144 threads
    const int u = ub >> 5;
    const int i = tid / 12, j = tid % 12;

    if (tid < 21) {
        float s = 0.f;
        #pragma unroll
        for (int p = 0; p < 4; ++p) s += g_win[(ub * 4 + p) * 21 + tid];
        win[tid] = s;
    }
    if (tid == 21) {
        float s = 0.f;
        #pragma unroll
        for (int p = 0; p < 4; ++p) s += g_noise[ub * 4 + p];
        s_sh = s / (64.0f * 1631.0f * 2.0f);
    }
    __syncthreads();

    if (tid == 0) {
        int bi = 0; float bv = win[0];
        for (int q = 1; q < 21; ++q) if (win[q] > bv) { bv = win[q]; bi = q; }
        int k12 = (12 - (cs[u] % 12)) % 12; if (k12 < 0) k12 += 12;
        g_m[ub] = k12 * 136 + (bi - 10);
    }

    int d = i - j; if (d < 0) d = -d;
    float c = (float)pow(0.9, (double)d);
    Cm[tid] = c;
    Am[tid] = c + ((i == j) ? s_sh : 0.f);
    Iv[tid] = (i == j) ? 1.f : 0.f;
    __syncthreads();

    for (int k = 0; k < 12; ++k) {
        float piv = Am[k * 12 + k];
        __syncthreads();
        if (i == k) {
            float ip = 1.0f / piv;
            Am[tid] *= ip; Iv[tid] *= ip;
        }
        __syncthreads();
        float f   = Am[i * 12 + k];
        float akj = Am[k * 12 + j];
        float ikj = Iv[k * 12 + j];
        __syncthreads();
        if (i != k) {
            Am[tid] = fmaf(-f, akj, Am[tid]);
            Iv[tid] = fmaf(-f, ikj, Iv[tid]);
        }
        __syncthreads();
    }

    float w = 0.f;
    #pragma unroll
    for (int k2 = 0; k2 < 12; ++k2) w = fmaf(Cm[i * 12 + k2], Iv[k2 * 12 + j], w);
    Wsh[tid] = w;
    __syncthreads();

    // Weff[class][i][s] = sum_j W[i][j] * Lerp[class][j][s], packed {w,w}
    for (int item = tid; item < 180; item += 144) {
        const int cl  = item / 60;
        const int rem = item - cl * 60;
        const int ii  = rem / 5;
        const int s   = rem - ii * 5;
        const int rep = (cl == 0) ? 0 : ((cl == 1) ? 1 : 135);
        const int hb  = 3 * rep - 1;
        float acc = 0.f;
        #pragma unroll
        for (int jj = 0; jj < 12; ++jj) {
            float t = (float)(rep * 12 + jj);
            float p = (t - 1.5f) * 0.25f;
            p = fminf(fmaxf(p, 0.f), 407.f);
            int i0 = (int)p; if (i0 > 406) i0 = 406;
            float fr = p - (float)i0;
            int s0 = i0 - hb;
            float coef = (s == s0) ? (1.f - fr) : ((s == s0 + 1) ? fr : 0.f);
            acc = fmaf(Wsh[ii * 12 + jj], coef, acc);
        }
        g_Weff2[ub * 180 + item] = pk2(acc, acc);
    }
}

// ---------------- kernel B: phase + 4-avg + folded 5-tap stencil -------------
__global__ __launch_bounds__(256) void kB(const float* __restrict__ lsr,
                                          const float* __restrict__ lsi,
                                          float2* __restrict__ out) {
    __shared__ float2 ph[LL];
    __shared__ ull    hv[RWS * RED];    // packed {hr,hi}
    __shared__ ull    We2[180];

    const int tid  = threadIdx.x;
    const int row0 = blockIdx.x * RWS;      // RWS rows, same ub
    const int ub   = row0 >> 6;

    if (tid < 180) We2[tid] = g_Weff2[ub * 180 + tid];
    const int m  = g_m[ub];
    const int mm = ((m % LL) + LL) % LL;

    // incremental phase table fill: q = (n*mm) % LL
    {
        int q = (tid * mm) % LL;
        const int stp = (256 * mm) % LL;
        for (int n = tid; n < LL; n += 256) {
            ph[n] = g_phtab[q];
            q += stp; if (q >= LL) q -= LL;
        }
    }
    __syncthreads();

    // stage 1: phase-shifted 4-tap average
    for (int item = tid; item < RWS * RED; item += 256) {
        const int rl = item / RED;
        const int rr = item - rl * RED;
        const int base = (row0 + rl) * LL + 4 * rr;
        const float4 xr = *(const float4*)(lsr + base);
        const float4 xi = *(const float4*)(lsi + base);
        const float2 p0 = ph[4*rr], p1 = ph[4*rr+1], p2 = ph[4*rr+2], p3 = ph[4*rr+3];
        float sr, si;
        sr = xr.x * p0.x;              si = xr.x * p0.y;
        sr = fmaf(-xi.x, p0.y, sr);    si = fmaf( xi.x, p0.x, si);
        sr = fmaf( xr.y, p1.x, sr);    si = fmaf( xr.y, p1.y, si);
        sr = fmaf(-xi.y, p1.y, sr);    si = fmaf( xi.y, p1.x, si);
        sr = fmaf( xr.z, p2.x, sr);    si = fmaf( xr.z, p2.y, si);
        sr = fmaf(-xi.z, p2.y, sr);    si = fmaf( xi.z, p2.x, si);
        sr = fmaf( xr.w, p3.x, sr);    si = fmaf( xr.w, p3.y, si);
        sr = fmaf(-xi.w, p3.y, sr);    si = fmaf( xi.w, p3.x, si);
        hv[rl * RED + rr] = pk2(sr * 0.25f, si * 0.25f);
    }
    __syncthreads();

    // stage 2: per (row, blk) item -> 12 outputs via packed 5-tap stencil
    for (int item = tid; item < RWS * 136; item += 256) {
        const int rl  = item / 136;
        const int blk = item - rl * 136;
        const int cl  = (blk == 0) ? 0 : ((blk == 135) ? 2 : 1);
        const ull* w  = &We2[cl * 60];
        const int hb  = 3 * blk - 1;
        const int hbase = rl * RED;

        ull h[5];
        #pragma unroll
        for (int s = 0; s < 5; ++s) {
            int idx = hb + s;
            idx = (idx < 0) ? 0 : ((idx > RED - 1) ? RED - 1 : idx);
            h[s] = hv[hbase + idx];
        }

        float2 res[12];
        #pragma unroll
        for (int i = 0; i < 12; ++i) {
            ull acc = mul2_(w[i * 5], h[0]);
            acc = fma2_(w[i * 5 + 1], h[1], acc);
            acc = fma2_(w[i * 5 + 2], h[2], acc);
            acc = fma2_(w[i * 5 + 3], h[3], acc);
            acc = fma2_(w[i * 5 + 4], h[4], acc);
            res[i] = up2(acc);
        }

        float4* op = (float4*)(out + (row0 + rl) * LL + blk * 12);
        #pragma unroll
        for (int q = 0; q < 6; ++q)
            op[q] = make_float4(res[2*q].x, res[2*q].y, res[2*q+1].x, res[2*q+1].y);
    }
}

// ---------------- launcher ----------------------------------------------------
extern "C" void kernel_launch(void* const* d_in, const int* in_sizes, int n_in,
                              void* d_out, int out_size) {
    const float* lsr = (const float*)d_in[0];
    const float* lsi = (const float*)d_in[1];
    const int*   cs  = (const int*)d_in[2];
    float2* out = (float2*)d_out;

    kP<<<7, 256>>>();
    kA<<<1024, 256>>>(lsr, lsi, cs);
    kS<<<NUP * NB, 144>>>(cs);
    kB<<<NUP * NB * NA / RWS, 256>>>(lsr, lsi, out);
    (void)in_sizes; (void)n_in; (void)out_size;
}